// round 1
// baseline (speedup 1.0000x reference)
#include <cuda_runtime.h>
#include <math.h>

// ---------------------------------------------------------------------------
// Problem constants:  x[B=4,S=4,L=1024,F=256]; D=256, H=8, DH=32; N = B*S = 16
// ---------------------------------------------------------------------------
#define NSEQ 16
#define LSEQ 1024
#define FDIM 256
#define DDIM 256
#define NHEAD 8
#define DH 32
#define MROWS (NSEQ * LSEQ)   // 16384

// Scratch (device globals — no runtime allocation allowed)
__device__ float g_Q[MROWS * DDIM];
__device__ float g_K[MROWS * DDIM];
__device__ float g_V[MROWS * DDIM];
__device__ float g_A[MROWS * DDIM];   // attention output (pre-O-proj)
__device__ float g_O[MROWS * DDIM];   // O-projection output

// ---------------------------------------------------------------------------
// GEMM (NT): C[M,N] = A[M,K] @ W[N,K]^T + bias[N]
// BM=128, BN=64, BK=32, 256 threads, 8x4 microtile per thread.
// M=16384, N=256, K=256 here — all tile-divisible, no bounds checks.
// ---------------------------------------------------------------------------
#define BM 128
#define BN 64
#define BK 32

__global__ __launch_bounds__(256) void gemm_nt_bias(
    const float* __restrict__ A, const float* __restrict__ W,
    const float* __restrict__ bias, float* __restrict__ C,
    int M, int N, int K)
{
    __shared__ float As[BK][BM + 1];   // padded: conflict-free k-major stores
    __shared__ float Bs[BK][BN + 1];

    const int bm = blockIdx.y * BM;
    const int bn = blockIdx.x * BN;
    const int tid = threadIdx.x;          // 0..255
    const int tx = tid % 16;              // n-frag
    const int ty = tid / 16;              // m-frag

    float acc[8][4];
    #pragma unroll
    for (int i = 0; i < 8; i++)
        #pragma unroll
        for (int j = 0; j < 4; j++) acc[i][j] = 0.f;

    for (int k0 = 0; k0 < K; k0 += BK) {
        // Load A tile: 128x32 floats = 1024 float4, 4 per thread
        #pragma unroll
        for (int i = 0; i < 4; i++) {
            int v  = tid + i * 256;         // 0..1023
            int r  = v >> 3;                // row 0..127
            int c4 = (v & 7) << 2;          // k col (multiple of 4)
            float4 a = *reinterpret_cast<const float4*>(
                &A[(size_t)(bm + r) * K + k0 + c4]);
            As[c4 + 0][r] = a.x; As[c4 + 1][r] = a.y;
            As[c4 + 2][r] = a.z; As[c4 + 3][r] = a.w;
        }
        // Load B tile: 64x32 floats = 512 float4, 2 per thread
        #pragma unroll
        for (int i = 0; i < 2; i++) {
            int v  = tid + i * 256;         // 0..511
            int r  = v >> 3;                // row 0..63
            int c4 = (v & 7) << 2;
            float4 b = *reinterpret_cast<const float4*>(
                &W[(size_t)(bn + r) * K + k0 + c4]);
            Bs[c4 + 0][r] = b.x; Bs[c4 + 1][r] = b.y;
            Bs[c4 + 2][r] = b.z; Bs[c4 + 3][r] = b.w;
        }
        __syncthreads();

        #pragma unroll
        for (int k = 0; k < BK; k++) {
            float a[8], b[4];
            #pragma unroll
            for (int i = 0; i < 8; i++) a[i] = As[k][ty * 8 + i];
            #pragma unroll
            for (int j = 0; j < 4; j++) b[j] = Bs[k][tx * 4 + j];
            #pragma unroll
            for (int i = 0; i < 8; i++)
                #pragma unroll
                for (int j = 0; j < 4; j++) acc[i][j] += a[i] * b[j];
        }
        __syncthreads();
    }

    // Epilogue with bias, vectorized over n
    #pragma unroll
    for (int i = 0; i < 8; i++) {
        int row = bm + ty * 8 + i;
        int col = bn + tx * 4;
        float4 o;
        o.x = acc[i][0] + bias[col + 0];
        o.y = acc[i][1] + bias[col + 1];
        o.z = acc[i][2] + bias[col + 2];
        o.w = acc[i][3] + bias[col + 3];
        *reinterpret_cast<float4*>(&C[(size_t)row * N + col]) = o;
    }
}

// ---------------------------------------------------------------------------
// Flash attention: grid (L/128, H, N), 128 threads, 1 thread = 1 query row.
// q[32] and acc[32] live in registers; K/V in 32x32 smem tiles (broadcast
// reads); online softmax over 32 K/V tiles.
// ---------------------------------------------------------------------------
__global__ __launch_bounds__(128) void attn_kernel(
    const float* __restrict__ Q, const float* __restrict__ K,
    const float* __restrict__ V, float* __restrict__ A)
{
    const int qr = blockIdx.x * 128 + threadIdx.x;   // query row in [0,1024)
    const int h  = blockIdx.y;
    const int n  = blockIdx.z;
    const int h0 = h * DH;

    __shared__ float Ks[32][33];
    __shared__ float Vs[32][33];

    // Load q row (pre-scaled by 1/sqrt(DH))
    const float scale = 0.17677669529663687f;  // 1/sqrt(32)
    float q[DH];
    {
        const float4* Qp = reinterpret_cast<const float4*>(
            Q + ((size_t)n * LSEQ + qr) * DDIM + h0);
        #pragma unroll
        for (int i = 0; i < 8; i++) {
            float4 t = Qp[i];
            q[i * 4 + 0] = t.x * scale; q[i * 4 + 1] = t.y * scale;
            q[i * 4 + 2] = t.z * scale; q[i * 4 + 3] = t.w * scale;
        }
    }

    float acc[DH];
    #pragma unroll
    for (int d = 0; d < DH; d++) acc[d] = 0.f;
    float m = -INFINITY, lsum = 0.f;

    const float* Kb = K + (size_t)n * LSEQ * DDIM + h0;
    const float* Vb = V + (size_t)n * LSEQ * DDIM + h0;

    for (int t0 = 0; t0 < LSEQ; t0 += 32) {
        __syncthreads();
        // Cooperative tile load: 32 rows x 32 cols; warp covers one row → coalesced
        for (int i = threadIdx.x; i < 32 * 32; i += 128) {
            int r = i >> 5, c = i & 31;
            Ks[r][c] = Kb[(size_t)(t0 + r) * DDIM + c];
            Vs[r][c] = Vb[(size_t)(t0 + r) * DDIM + c];
        }
        __syncthreads();

        float s[32];
        #pragma unroll
        for (int j = 0; j < 32; j++) {
            float sj = 0.f;
            #pragma unroll
            for (int d = 0; d < DH; d++) sj += q[d] * Ks[j][d];  // smem broadcast
            s[j] = sj;
        }

        float mt = m;
        #pragma unroll
        for (int j = 0; j < 32; j++) mt = fmaxf(mt, s[j]);
        float corr = __expf(m - mt);   // first tile: exp(-inf)=0
        m = mt;
        lsum *= corr;
        #pragma unroll
        for (int d = 0; d < DH; d++) acc[d] *= corr;

        #pragma unroll
        for (int j = 0; j < 32; j++) {
            float p = __expf(s[j] - m);
            lsum += p;
            #pragma unroll
            for (int d = 0; d < DH; d++) acc[d] += p * Vs[j][d];
        }
    }

    float inv = 1.f / lsum;
    float4* Ap = reinterpret_cast<float4*>(
        A + ((size_t)n * LSEQ + qr) * DDIM + h0);
    #pragma unroll
    for (int i = 0; i < 8; i++) {
        float4 t;
        t.x = acc[i * 4 + 0] * inv; t.y = acc[i * 4 + 1] * inv;
        t.z = acc[i * 4 + 2] * inv; t.w = acc[i * 4 + 3] * inv;
        Ap[i] = t;
    }
}

// ---------------------------------------------------------------------------
// Softmax pooling over L per (n, d):  out[n,d] = sum_l O[n,l,d]*softmax_l(O)
// grid (D/32, N), 256 threads = 32 d-cols x 8 l-groups, online softmax.
// ---------------------------------------------------------------------------
__global__ __launch_bounds__(256) void pool_kernel(
    const float* __restrict__ O, float* __restrict__ out)
{
    const int n  = blockIdx.y;
    const int d0 = blockIdx.x * 32;
    const int dc = threadIdx.x & 31;
    const int g  = threadIdx.x >> 5;     // 0..7
    const int d  = d0 + dc;

    float m = -INFINITY, se = 0.f, sex = 0.f;
    for (int l = g; l < LSEQ; l += 8) {
        float x = O[((size_t)n * LSEQ + l) * DDIM + d];
        if (x > m) {
            float c = __expf(m - x);
            se *= c; sex *= c; m = x;
        }
        float p = __expf(x - m);
        se += p; sex += p * x;
    }

    __shared__ float sm[8][32], sse[8][32], ssex[8][32];
    sm[g][dc] = m; sse[g][dc] = se; ssex[g][dc] = sex;
    __syncthreads();

    if (g == 0) {
        #pragma unroll
        for (int o = 1; o < 8; o++) {
            float m2 = sm[o][dc], se2 = sse[o][dc], sex2 = ssex[o][dc];
            if (m2 > m) {
                float c = __expf(m - m2);
                se *= c; sex *= c; m = m2;
            }
            float c2 = __expf(m2 - m);
            se += se2 * c2; sex += sex2 * c2;
        }
        out[(size_t)n * DDIM + d] = sex / se;
    }
}

// ---------------------------------------------------------------------------
// Launch: QKV GEMMs -> attention -> O GEMM -> pooling
// Inputs (metadata order): x, Wq, bq, Wk, bk, Wv, bv, Wo, bo
// ---------------------------------------------------------------------------
extern "C" void kernel_launch(void* const* d_in, const int* in_sizes, int n_in,
                              void* d_out, int out_size)
{
    const float* x  = (const float*)d_in[0];
    const float* Wq = (const float*)d_in[1];
    const float* bq = (const float*)d_in[2];
    const float* Wk = (const float*)d_in[3];
    const float* bk = (const float*)d_in[4];
    const float* Wv = (const float*)d_in[5];
    const float* bv = (const float*)d_in[6];
    const float* Wo = (const float*)d_in[7];
    const float* bo = (const float*)d_in[8];
    float* out = (float*)d_out;

    float *Q, *K, *V, *A, *O;
    cudaGetSymbolAddress((void**)&Q, g_Q);
    cudaGetSymbolAddress((void**)&K, g_K);
    cudaGetSymbolAddress((void**)&V, g_V);
    cudaGetSymbolAddress((void**)&A, g_A);
    cudaGetSymbolAddress((void**)&O, g_O);

    dim3 gThreads(256);
    dim3 gGrid(DDIM / BN, MROWS / BM);   // (4, 128)

    gemm_nt_bias<<<gGrid, gThreads>>>(x, Wq, bq, Q, MROWS, DDIM, FDIM);
    gemm_nt_bias<<<gGrid, gThreads>>>(x, Wk, bk, K, MROWS, DDIM, FDIM);
    gemm_nt_bias<<<gGrid, gThreads>>>(x, Wv, bv, V, MROWS, DDIM, FDIM);

    dim3 aGrid(LSEQ / 128, NHEAD, NSEQ); // (8, 8, 16)
    attn_kernel<<<aGrid, 128>>>(Q, K, V, A);

    gemm_nt_bias<<<gGrid, gThreads>>>(A, Wo, bo, O, MROWS, DDIM, DDIM);

    dim3 pGrid(DDIM / 32, NSEQ);         // (8, 16)
    pool_kernel<<<pGrid, 256>>>(O, out);
}

// round 2
// speedup vs baseline: 1.0072x; 1.0072x over previous
#include <cuda_runtime.h>
#include <math.h>

// ---------------------------------------------------------------------------
// Problem constants:  x[B=4,S=4,L=1024,F=256]; D=256, H=8, DH=32; N = B*S = 16
// ---------------------------------------------------------------------------
#define NSEQ 16
#define LSEQ 1024
#define FDIM 256
#define DDIM 256
#define NHEAD 8
#define DH 32
#define MROWS (NSEQ * LSEQ)   // 16384

// Scratch (device globals — no runtime allocation allowed)
__device__ float g_Q[MROWS * DDIM];
__device__ float g_K[MROWS * DDIM];
__device__ float g_V[MROWS * DDIM];
__device__ float g_A[MROWS * DDIM];   // attention output (pre-O-proj)
__device__ float g_O[MROWS * DDIM];   // O-projection output

// ---------------------------------------------------------------------------
// GEMM (NT): C[M,N] = A[M,K] @ W[N,K]^T + bias[N]
// BM=128, BN=64, BK=32, 256 threads, 8x4 microtile per thread.
// ---------------------------------------------------------------------------
#define BM 128
#define BN 64
#define BK 32

__global__ __launch_bounds__(256) void gemm_nt_bias(
    const float* __restrict__ A, const float* __restrict__ W,
    const float* __restrict__ bias, float* __restrict__ C,
    int M, int N, int K)
{
    __shared__ float As[BK][BM + 1];   // padded: conflict-free k-major stores
    __shared__ float Bs[BK][BN + 1];

    const int bm = blockIdx.y * BM;
    const int bn = blockIdx.x * BN;
    const int tid = threadIdx.x;          // 0..255
    const int tx = tid % 16;              // n-frag
    const int ty = tid / 16;              // m-frag

    float acc[8][4];
    #pragma unroll
    for (int i = 0; i < 8; i++)
        #pragma unroll
        for (int j = 0; j < 4; j++) acc[i][j] = 0.f;

    for (int k0 = 0; k0 < K; k0 += BK) {
        #pragma unroll
        for (int i = 0; i < 4; i++) {
            int v  = tid + i * 256;         // 0..1023
            int r  = v >> 3;                // row 0..127
            int c4 = (v & 7) << 2;          // k col (multiple of 4)
            float4 a = *reinterpret_cast<const float4*>(
                &A[(size_t)(bm + r) * K + k0 + c4]);
            As[c4 + 0][r] = a.x; As[c4 + 1][r] = a.y;
            As[c4 + 2][r] = a.z; As[c4 + 3][r] = a.w;
        }
        #pragma unroll
        for (int i = 0; i < 2; i++) {
            int v  = tid + i * 256;         // 0..511
            int r  = v >> 3;                // row 0..63
            int c4 = (v & 7) << 2;
            float4 b = *reinterpret_cast<const float4*>(
                &W[(size_t)(bn + r) * K + k0 + c4]);
            Bs[c4 + 0][r] = b.x; Bs[c4 + 1][r] = b.y;
            Bs[c4 + 2][r] = b.z; Bs[c4 + 3][r] = b.w;
        }
        __syncthreads();

        #pragma unroll
        for (int k = 0; k < BK; k++) {
            float a[8], b[4];
            #pragma unroll
            for (int i = 0; i < 8; i++) a[i] = As[k][ty * 8 + i];
            #pragma unroll
            for (int j = 0; j < 4; j++) b[j] = Bs[k][tx * 4 + j];
            #pragma unroll
            for (int i = 0; i < 8; i++)
                #pragma unroll
                for (int j = 0; j < 4; j++) acc[i][j] += a[i] * b[j];
        }
        __syncthreads();
    }

    #pragma unroll
    for (int i = 0; i < 8; i++) {
        int row = bm + ty * 8 + i;
        int col = bn + tx * 4;
        float4 o;
        o.x = acc[i][0] + bias[col + 0];
        o.y = acc[i][1] + bias[col + 1];
        o.z = acc[i][2] + bias[col + 2];
        o.w = acc[i][3] + bias[col + 3];
        *reinterpret_cast<float4*>(&C[(size_t)row * N + col]) = o;
    }
}

// ---------------------------------------------------------------------------
// Flash attention: grid (L/128, H, N), 128 threads, 1 thread = 1 query row.
// K/V tiles 32x32 in UNPADDED smem; all smem reads are float4 broadcasts
// (LDS.128) -> 4 FMAs per LDS instead of 1. Rows are 128B so float4-aligned;
// broadcast reads have no bank conflicts by definition.
// ---------------------------------------------------------------------------
__global__ __launch_bounds__(128) void attn_kernel(
    const float* __restrict__ Q, const float* __restrict__ K,
    const float* __restrict__ V, float* __restrict__ A)
{
    const int qr = blockIdx.x * 128 + threadIdx.x;   // query row in [0,1024)
    const int h  = blockIdx.y;
    const int n  = blockIdx.z;
    const int h0 = h * DH;

    __shared__ __align__(16) float Ks[32][32];
    __shared__ __align__(16) float Vs[32][32];

    const float scale = 0.17677669529663687f;  // 1/sqrt(32)
    float4 q[8];
    {
        const float4* Qp = reinterpret_cast<const float4*>(
            Q + ((size_t)n * LSEQ + qr) * DDIM + h0);
        #pragma unroll
        for (int i = 0; i < 8; i++) {
            float4 t = Qp[i];
            t.x *= scale; t.y *= scale; t.z *= scale; t.w *= scale;
            q[i] = t;
        }
    }

    float4 acc[8];
    #pragma unroll
    for (int i = 0; i < 8; i++) acc[i] = make_float4(0.f, 0.f, 0.f, 0.f);
    float m = -INFINITY, lsum = 0.f;

    const float* Kb = K + (size_t)n * LSEQ * DDIM + h0;
    const float* Vb = V + (size_t)n * LSEQ * DDIM + h0;

    for (int t0 = 0; t0 < LSEQ; t0 += 32) {
        __syncthreads();
        // Cooperative tile fill, vectorized: 32x32 floats = 256 float4 per
        // array, 2 per thread per array. Consecutive threads hit consecutive
        // 16B chunks -> coalesced gmem, conflict-free smem.
        {
            float4* Ks4 = reinterpret_cast<float4*>(&Ks[0][0]);
            float4* Vs4 = reinterpret_cast<float4*>(&Vs[0][0]);
            #pragma unroll
            for (int i = 0; i < 2; i++) {
                int v = threadIdx.x + i * 128;   // 0..255
                int r = v >> 3;                  // row 0..31
                int c = v & 7;                   // float4 col 0..7
                Ks4[v] = *reinterpret_cast<const float4*>(
                    &Kb[(size_t)(t0 + r) * DDIM + c * 4]);
                Vs4[v] = *reinterpret_cast<const float4*>(
                    &Vb[(size_t)(t0 + r) * DDIM + c * 4]);
            }
        }
        __syncthreads();

        // Scores: s[j] = q . Ks[j]  via float4 broadcast reads
        float s[32];
        #pragma unroll
        for (int j = 0; j < 32; j++) {
            const float4* kr = reinterpret_cast<const float4*>(&Ks[j][0]);
            float sj = 0.f;
            #pragma unroll
            for (int d = 0; d < 8; d++) {
                float4 kv = kr[d];
                sj += q[d].x * kv.x + q[d].y * kv.y
                    + q[d].z * kv.z + q[d].w * kv.w;
            }
            s[j] = sj;
        }

        float mt = m;
        #pragma unroll
        for (int j = 0; j < 32; j++) mt = fmaxf(mt, s[j]);
        float corr = __expf(m - mt);   // first tile: exp(-inf)=0
        m = mt;
        lsum *= corr;
        #pragma unroll
        for (int i = 0; i < 8; i++) {
            acc[i].x *= corr; acc[i].y *= corr;
            acc[i].z *= corr; acc[i].w *= corr;
        }

        #pragma unroll
        for (int j = 0; j < 32; j++) {
            float p = __expf(s[j] - m);
            lsum += p;
            const float4* vr = reinterpret_cast<const float4*>(&Vs[j][0]);
            #pragma unroll
            for (int d = 0; d < 8; d++) {
                float4 vv = vr[d];
                acc[d].x += p * vv.x; acc[d].y += p * vv.y;
                acc[d].z += p * vv.z; acc[d].w += p * vv.w;
            }
        }
    }

    float inv = 1.f / lsum;
    float4* Ap = reinterpret_cast<float4*>(
        A + ((size_t)n * LSEQ + qr) * DDIM + h0);
    #pragma unroll
    for (int i = 0; i < 8; i++) {
        float4 t = acc[i];
        t.x *= inv; t.y *= inv; t.z *= inv; t.w *= inv;
        Ap[i] = t;
    }
}

// ---------------------------------------------------------------------------
// Softmax pooling over L per (n, d):  out[n,d] = sum_l O[n,l,d]*softmax_l(O)
// ---------------------------------------------------------------------------
__global__ __launch_bounds__(256) void pool_kernel(
    const float* __restrict__ O, float* __restrict__ out)
{
    const int n  = blockIdx.y;
    const int d0 = blockIdx.x * 32;
    const int dc = threadIdx.x & 31;
    const int g  = threadIdx.x >> 5;     // 0..7
    const int d  = d0 + dc;

    float m = -INFINITY, se = 0.f, sex = 0.f;
    for (int l = g; l < LSEQ; l += 8) {
        float x = O[((size_t)n * LSEQ + l) * DDIM + d];
        if (x > m) {
            float c = __expf(m - x);
            se *= c; sex *= c; m = x;
        }
        float p = __expf(x - m);
        se += p; sex += p * x;
    }

    __shared__ float sm[8][32], sse[8][32], ssex[8][32];
    sm[g][dc] = m; sse[g][dc] = se; ssex[g][dc] = sex;
    __syncthreads();

    if (g == 0) {
        #pragma unroll
        for (int o = 1; o < 8; o++) {
            float m2 = sm[o][dc], se2 = sse[o][dc], sex2 = ssex[o][dc];
            if (m2 > m) {
                float c = __expf(m - m2);
                se *= c; sex *= c; m = m2;
            }
            float c2 = __expf(m2 - m);
            se += se2 * c2; sex += sex2 * c2;
        }
        out[(size_t)n * DDIM + d] = sex / se;
    }
}

// ---------------------------------------------------------------------------
// Launch: QKV GEMMs -> attention -> O GEMM -> pooling
// Inputs (metadata order): x, Wq, bq, Wk, bk, Wv, bv, Wo, bo
// ---------------------------------------------------------------------------
extern "C" void kernel_launch(void* const* d_in, const int* in_sizes, int n_in,
                              void* d_out, int out_size)
{
    const float* x  = (const float*)d_in[0];
    const float* Wq = (const float*)d_in[1];
    const float* bq = (const float*)d_in[2];
    const float* Wk = (const float*)d_in[3];
    const float* bk = (const float*)d_in[4];
    const float* Wv = (const float*)d_in[5];
    const float* bv = (const float*)d_in[6];
    const float* Wo = (const float*)d_in[7];
    const float* bo = (const float*)d_in[8];
    float* out = (float*)d_out;

    float *Q, *K, *V, *A, *O;
    cudaGetSymbolAddress((void**)&Q, g_Q);
    cudaGetSymbolAddress((void**)&K, g_K);
    cudaGetSymbolAddress((void**)&V, g_V);
    cudaGetSymbolAddress((void**)&A, g_A);
    cudaGetSymbolAddress((void**)&O, g_O);

    dim3 gThreads(256);
    dim3 gGrid(DDIM / BN, MROWS / BM);   // (4, 128)

    gemm_nt_bias<<<gGrid, gThreads>>>(x, Wq, bq, Q, MROWS, DDIM, FDIM);
    gemm_nt_bias<<<gGrid, gThreads>>>(x, Wk, bk, K, MROWS, DDIM, FDIM);
    gemm_nt_bias<<<gGrid, gThreads>>>(x, Wv, bv, V, MROWS, DDIM, FDIM);

    dim3 aGrid(LSEQ / 128, NHEAD, NSEQ); // (8, 8, 16)
    attn_kernel<<<aGrid, 128>>>(Q, K, V, A);

    gemm_nt_bias<<<gGrid, gThreads>>>(A, Wo, bo, O, MROWS, DDIM, DDIM);

    dim3 pGrid(DDIM / 32, NSEQ);         // (8, 16)
    pool_kernel<<<pGrid, 256>>>(O, out);
}

// round 4
// speedup vs baseline: 2.6774x; 2.6583x over previous
#include <cuda_runtime.h>
#include <cuda_fp16.h>
#include <math.h>
#include <cstdint>

// ---------------------------------------------------------------------------
// Problem constants:  x[B=4,S=4,L=1024,F=256]; D=256, H=8, DH=32; N = B*S = 16
// ---------------------------------------------------------------------------
#define NSEQ 16
#define LSEQ 1024
#define DDIM 256
#define NHEAD 8
#define MROWS (NSEQ * LSEQ)   // 16384

// Scratch (device globals — no runtime allocation allowed).
// Split format: each element is u32 = (lo_fp16 << 16) | hi_fp16,
// where value ~= hi + lo (2-term fp16 split => ~22 mantissa bits).
__device__ uint32_t g_X2[MROWS * DDIM];
__device__ uint32_t g_Q2[MROWS * DDIM];
__device__ uint32_t g_K2[MROWS * DDIM];
__device__ uint32_t g_V2[MROWS * DDIM];
__device__ uint32_t g_A2[MROWS * DDIM];
__device__ uint32_t g_Wq2[DDIM * DDIM];
__device__ uint32_t g_Wk2[DDIM * DDIM];
__device__ uint32_t g_Wv2[DDIM * DDIM];
__device__ uint32_t g_Wo2[DDIM * DDIM];
__device__ float    g_O[MROWS * DDIM];

// ===========================================================================
// helpers
// ===========================================================================
__device__ __forceinline__ uint32_t smem_u32(const void* p) {
    uint32_t a;
    asm("{ .reg .u64 t; cvta.to.shared.u64 t, %1; cvt.u32.u64 %0, t; }"
        : "=r"(a) : "l"(p));
    return a;
}

__device__ __forceinline__ void ldmx4(uint32_t (&r)[4], uint32_t addr) {
    asm volatile("ldmatrix.sync.aligned.m8n8.x4.shared.b16 {%0,%1,%2,%3}, [%4];"
                 : "=r"(r[0]), "=r"(r[1]), "=r"(r[2]), "=r"(r[3]) : "r"(addr));
}
__device__ __forceinline__ void ldmx2(uint32_t (&r)[2], uint32_t addr) {
    asm volatile("ldmatrix.sync.aligned.m8n8.x2.shared.b16 {%0,%1}, [%2];"
                 : "=r"(r[0]), "=r"(r[1]) : "r"(addr));
}

// D (f32) += A (f16) x B (f16), m16n8k16, A row-major, B col-major
__device__ __forceinline__ void mma16816(float (&c)[4], const uint32_t (&a)[4],
                                         const uint32_t (&b)[2]) {
    asm volatile(
        "mma.sync.aligned.m16n8k16.row.col.f32.f16.f16.f32 "
        "{%0,%1,%2,%3}, {%4,%5,%6,%7}, {%8,%9}, {%0,%1,%2,%3};"
        : "+f"(c[0]), "+f"(c[1]), "+f"(c[2]), "+f"(c[3])
        : "r"(a[0]), "r"(a[1]), "r"(a[2]), "r"(a[3]), "r"(b[0]), "r"(b[1]));
}

__device__ __forceinline__ uint32_t splitpack(float x) {
    __half h = __float2half_rn(x);
    __half l = __float2half_rn(x - __half2float(h));
    return (uint32_t)__half_as_ushort(h) | ((uint32_t)__half_as_ushort(l) << 16);
}
// split two floats into a hi-pair reg and a lo-pair reg (for mma A operands)
__device__ __forceinline__ void split2(float x0, float x1,
                                       uint32_t& hi, uint32_t& lo) {
    __half h0 = __float2half_rn(x0), h1 = __float2half_rn(x1);
    __half l0 = __float2half_rn(x0 - __half2float(h0));
    __half l1 = __float2half_rn(x1 - __half2float(h1));
    hi = (uint32_t)__half_as_ushort(h0) | ((uint32_t)__half_as_ushort(h1) << 16);
    lo = (uint32_t)__half_as_ushort(l0) | ((uint32_t)__half_as_ushort(l1) << 16);
}

// ===========================================================================
// split conversion:  dst[i] = splitpack(src[i])
// ===========================================================================
__global__ __launch_bounds__(256) void split_kernel(
    const float* __restrict__ src, uint32_t* __restrict__ dst, int n)
{
    int i = blockIdx.x * 256 + threadIdx.x;
    if (i < n) dst[i] = splitpack(src[i]);
}

// ===========================================================================
// GEMM via mma.sync, 3-term fp16 split:
// C[M,256] = A[M,256] @ W[256,256]^T + bias  (A,W in split-u32 format)
// CTA 128x128 tile, 8 warps (4m x 2n), warp tile 32x64. K chunks of 32.
// out_split: 1 -> write split-u32 (scaled), 0 -> write f32 (scaled).
// ===========================================================================
__global__ __launch_bounds__(256) void gemm_mma(
    const uint32_t* __restrict__ A2, const uint32_t* __restrict__ W2,
    const float* __restrict__ bias, void* __restrict__ Cout,
    float outscale, int out_split)
{
    __shared__ __align__(16) __half Ah[128][40];   // 32 data + 8 pad halfs
    __shared__ __align__(16) __half Al[128][40];
    __shared__ __align__(16) __half Wh[128][40];
    __shared__ __align__(16) __half Wl[128][40];

    const int tid  = threadIdx.x;
    const int lane = tid & 31;
    const int wid  = tid >> 5;
    const int wm   = wid & 3;          // 0..3 (m block of 32)
    const int wn   = wid >> 2;         // 0..1 (n block of 64)
    const int bm   = blockIdx.y * 128;
    const int bn   = blockIdx.x * 128;

    float acc[2][8][4];
    #pragma unroll
    for (int i = 0; i < 2; i++)
        #pragma unroll
        for (int j = 0; j < 8; j++)
            #pragma unroll
            for (int k = 0; k < 4; k++) acc[i][j][k] = 0.f;

    // precompute ldmatrix addresses (constant across chunks except ks)
    const uint32_t a_base = smem_u32(&Ah[0][0]);
    const uint32_t l_base = smem_u32(&Al[0][0]);
    const uint32_t wh_base = smem_u32(&Wh[0][0]);
    const uint32_t wl_base = smem_u32(&Wl[0][0]);
    const int a_row = wm * 32 + (lane & 7) + ((lane >> 3) & 1) * 8; // + mt*16
    const int a_col = (lane >> 4) * 8;                              // + ks
    const int b_row = wn * 64 + (lane & 7);                         // + nt*8
    const int b_col = ((lane >> 3) & 1) * 8;                        // + ks

    #pragma unroll 1
    for (int kc = 0; kc < 8; kc++) {
        const int k0 = kc * 32;
        // ---- load + deinterleave A chunk (128x32 u32 = 1024 uint4)
        #pragma unroll
        for (int i = 0; i < 4; i++) {
            int idx = tid + i * 256;
            int r = idx >> 3, cg = idx & 7;
            uint4 e = *reinterpret_cast<const uint4*>(
                &A2[(size_t)(bm + r) * 256 + k0 + cg * 4]);
            uint32_t h01 = (e.x & 0xFFFFu) | ((e.y & 0xFFFFu) << 16);
            uint32_t h23 = (e.z & 0xFFFFu) | ((e.w & 0xFFFFu) << 16);
            uint32_t l01 = (e.x >> 16) | (e.y & 0xFFFF0000u);
            uint32_t l23 = (e.z >> 16) | (e.w & 0xFFFF0000u);
            *reinterpret_cast<uint2*>(&Ah[r][cg * 4]) = make_uint2(h01, h23);
            *reinterpret_cast<uint2*>(&Al[r][cg * 4]) = make_uint2(l01, l23);
        }
        // ---- load + deinterleave W chunk (rows bn..bn+128)
        #pragma unroll
        for (int i = 0; i < 4; i++) {
            int idx = tid + i * 256;
            int r = idx >> 3, cg = idx & 7;
            uint4 e = *reinterpret_cast<const uint4*>(
                &W2[(size_t)(bn + r) * 256 + k0 + cg * 4]);
            uint32_t h01 = (e.x & 0xFFFFu) | ((e.y & 0xFFFFu) << 16);
            uint32_t h23 = (e.z & 0xFFFFu) | ((e.w & 0xFFFFu) << 16);
            uint32_t l01 = (e.x >> 16) | (e.y & 0xFFFF0000u);
            uint32_t l23 = (e.z >> 16) | (e.w & 0xFFFF0000u);
            *reinterpret_cast<uint2*>(&Wh[r][cg * 4]) = make_uint2(h01, h23);
            *reinterpret_cast<uint2*>(&Wl[r][cg * 4]) = make_uint2(l01, l23);
        }
        __syncthreads();

        #pragma unroll
        for (int ks = 0; ks < 32; ks += 16) {
            uint32_t ah[2][4], al[2][4];
            #pragma unroll
            for (int mt = 0; mt < 2; mt++) {
                int off = (a_row + mt * 16) * 40 + a_col + ks;   // halfs
                ldmx4(ah[mt], a_base + off * 2);
                ldmx4(al[mt], l_base + off * 2);
            }
            uint32_t bh[8][2], bl[8][2];
            #pragma unroll
            for (int nt = 0; nt < 8; nt++) {
                int off = (b_row + nt * 8) * 40 + b_col + ks;
                ldmx2(bh[nt], wh_base + off * 2);
                ldmx2(bl[nt], wl_base + off * 2);
            }
            #pragma unroll
            for (int mt = 0; mt < 2; mt++)
                #pragma unroll
                for (int nt = 0; nt < 8; nt++) {
                    mma16816(acc[mt][nt], ah[mt], bh[nt]);
                    mma16816(acc[mt][nt], ah[mt], bl[nt]);
                    mma16816(acc[mt][nt], al[mt], bh[nt]);
                }
        }
        __syncthreads();
    }

    // ---- epilogue
    #pragma unroll
    for (int mt = 0; mt < 2; mt++) {
        #pragma unroll
        for (int nt = 0; nt < 8; nt++) {
            int r0 = bm + wm * 32 + mt * 16 + (lane >> 2);
            int c  = bn + wn * 64 + nt * 8 + (lane & 3) * 2;
            float b0 = bias[c], b1 = bias[c + 1];
            float v00 = (acc[mt][nt][0] + b0) * outscale;
            float v01 = (acc[mt][nt][1] + b1) * outscale;
            float v10 = (acc[mt][nt][2] + b0) * outscale;
            float v11 = (acc[mt][nt][3] + b1) * outscale;
            if (out_split) {
                uint32_t* C = reinterpret_cast<uint32_t*>(Cout);
                *reinterpret_cast<uint2*>(&C[(size_t)r0 * 256 + c]) =
                    make_uint2(splitpack(v00), splitpack(v01));
                *reinterpret_cast<uint2*>(&C[(size_t)(r0 + 8) * 256 + c]) =
                    make_uint2(splitpack(v10), splitpack(v11));
            } else {
                float* C = reinterpret_cast<float*>(Cout);
                *reinterpret_cast<float2*>(&C[(size_t)r0 * 256 + c]) =
                    make_float2(v00, v01);
                *reinterpret_cast<float2*>(&C[(size_t)(r0 + 8) * 256 + c]) =
                    make_float2(v10, v11);
            }
        }
    }
}

// ===========================================================================
// Flash attention via mma.sync (3-term fp16 split on QK^T and PV).
// grid (L/128, H, N), 128 threads / 4 warps; warp = 32 q-rows.
// K-tiles of 32 keys.  Q pre-scaled by 1/sqrt(DH) (baked in by Q-GEMM).
// ===========================================================================
__global__ __launch_bounds__(128) void attn_mma(
    const uint32_t* __restrict__ Q2, const uint32_t* __restrict__ K2,
    const uint32_t* __restrict__ V2, uint32_t* __restrict__ Aout)
{
    __shared__ __align__(16) __half Khi[32][40];
    __shared__ __align__(16) __half Klo[32][40];
    __shared__ __align__(16) __half Vthi[32][40];  // [dh][key]
    __shared__ __align__(16) __half Vtlo[32][40];

    const int tid  = threadIdx.x;
    const int lane = tid & 31;
    const int w    = tid >> 5;
    const int n    = blockIdx.z;
    const int h    = blockIdx.y;
    const int qbase = blockIdx.x * 128 + w * 32;
    const size_t seqoff = (size_t)n * LSEQ * 256 + h * 32;

    // ---- load Q fragments from global (split format), hi/lo
    uint32_t qh[2][2][4], ql[2][2][4];
    #pragma unroll
    for (int mt = 0; mt < 2; mt++)
        #pragma unroll
        for (int kt = 0; kt < 2; kt++)
            #pragma unroll
            for (int pi = 0; pi < 4; pi++) {
                int row = qbase + mt * 16 + (lane >> 2) + ((pi & 1) ? 8 : 0);
                int col = kt * 16 + (lane & 3) * 2 + ((pi & 2) ? 8 : 0);
                uint2 e = *reinterpret_cast<const uint2*>(
                    &Q2[seqoff + (size_t)row * 256 + col]);
                qh[mt][kt][pi] = (e.x & 0xFFFFu) | ((e.y & 0xFFFFu) << 16);
                ql[mt][kt][pi] = (e.x >> 16) | (e.y & 0xFFFF0000u);
            }

    float out[2][4][4];
    #pragma unroll
    for (int i = 0; i < 2; i++)
        #pragma unroll
        for (int j = 0; j < 4; j++)
            #pragma unroll
            for (int k = 0; k < 4; k++) out[i][j][k] = 0.f;
    float mrow[4]  = {-INFINITY, -INFINITY, -INFINITY, -INFINITY};
    float lpart[4] = {0.f, 0.f, 0.f, 0.f};

    const uint32_t kh_base = smem_u32(&Khi[0][0]);
    const uint32_t kl_base = smem_u32(&Klo[0][0]);
    const uint32_t vh_base = smem_u32(&Vthi[0][0]);
    const uint32_t vl_base = smem_u32(&Vtlo[0][0]);
    const int b_row = lane & 7;               // + nt*8
    const int b_col = ((lane >> 3) & 1) * 8;  // + kstep*16

    #pragma unroll 1
    for (int kt0 = 0; kt0 < LSEQ; kt0 += 32) {
        __syncthreads();
        // ---- K tile: 32 keys x 32 dh (u32) = 256 uint4, 2 per thread
        #pragma unroll
        for (int i = 0; i < 2; i++) {
            int idx = tid + i * 128;
            int r = idx >> 3, cg = idx & 7;
            uint4 e = *reinterpret_cast<const uint4*>(
                &K2[seqoff + (size_t)(kt0 + r) * 256 + cg * 4]);
            uint32_t h01 = (e.x & 0xFFFFu) | ((e.y & 0xFFFFu) << 16);
            uint32_t h23 = (e.z & 0xFFFFu) | ((e.w & 0xFFFFu) << 16);
            uint32_t l01 = (e.x >> 16) | (e.y & 0xFFFF0000u);
            uint32_t l23 = (e.z >> 16) | (e.w & 0xFFFF0000u);
            *reinterpret_cast<uint2*>(&Khi[r][cg * 4]) = make_uint2(h01, h23);
            *reinterpret_cast<uint2*>(&Klo[r][cg * 4]) = make_uint2(l01, l23);
        }
        // ---- V tile, transposed into [dh][key]
        #pragma unroll
        for (int i = 0; i < 2; i++) {
            int idx = tid + i * 128;
            int r = idx >> 3, cg = idx & 7;
            uint4 e = *reinterpret_cast<const uint4*>(
                &V2[seqoff + (size_t)(kt0 + r) * 256 + cg * 4]);
            int c0 = cg * 4;
            Vthi[c0 + 0][r] = __ushort_as_half((unsigned short)(e.x & 0xFFFFu));
            Vthi[c0 + 1][r] = __ushort_as_half((unsigned short)(e.y & 0xFFFFu));
            Vthi[c0 + 2][r] = __ushort_as_half((unsigned short)(e.z & 0xFFFFu));
            Vthi[c0 + 3][r] = __ushort_as_half((unsigned short)(e.w & 0xFFFFu));
            Vtlo[c0 + 0][r] = __ushort_as_half((unsigned short)(e.x >> 16));
            Vtlo[c0 + 1][r] = __ushort_as_half((unsigned short)(e.y >> 16));
            Vtlo[c0 + 2][r] = __ushort_as_half((unsigned short)(e.z >> 16));
            Vtlo[c0 + 3][r] = __ushort_as_half((unsigned short)(e.w >> 16));
        }
        __syncthreads();

        // ---- scores S[32 q, 32 k]
        float sc[2][4][4];
        #pragma unroll
        for (int i = 0; i < 2; i++)
            #pragma unroll
            for (int j = 0; j < 4; j++)
                #pragma unroll
                for (int k = 0; k < 4; k++) sc[i][j][k] = 0.f;

        #pragma unroll
        for (int kt = 0; kt < 2; kt++) {
            uint32_t bh[4][2], bl[4][2];
            #pragma unroll
            for (int nt = 0; nt < 4; nt++) {
                int off = (b_row + nt * 8) * 40 + b_col + kt * 16;
                ldmx2(bh[nt], kh_base + off * 2);
                ldmx2(bl[nt], kl_base + off * 2);
            }
            #pragma unroll
            for (int mt = 0; mt < 2; mt++)
                #pragma unroll
                for (int nt = 0; nt < 4; nt++) {
                    mma16816(sc[mt][nt], qh[mt][kt], bh[nt]);
                    mma16816(sc[mt][nt], qh[mt][kt], bl[nt]);
                    mma16816(sc[mt][nt], ql[mt][kt], bh[nt]);
                }
        }

        // ---- online softmax (4 row-slots per thread)
        #pragma unroll
        for (int s = 0; s < 4; s++) {
            int mt = s >> 1, hf = s & 1;
            float vmax = -INFINITY;
            #pragma unroll
            for (int nt = 0; nt < 4; nt++) {
                vmax = fmaxf(vmax, sc[mt][nt][hf * 2]);
                vmax = fmaxf(vmax, sc[mt][nt][hf * 2 + 1]);
            }
            vmax = fmaxf(vmax, __shfl_xor_sync(0xffffffffu, vmax, 1));
            vmax = fmaxf(vmax, __shfl_xor_sync(0xffffffffu, vmax, 2));
            float mnew = fmaxf(mrow[s], vmax);
            float corr = __expf(mrow[s] - mnew);
            mrow[s] = mnew;
            float psum = 0.f;
            #pragma unroll
            for (int nt = 0; nt < 4; nt++) {
                float p0 = __expf(sc[mt][nt][hf * 2] - mnew);
                float p1 = __expf(sc[mt][nt][hf * 2 + 1] - mnew);
                sc[mt][nt][hf * 2]     = p0;
                sc[mt][nt][hf * 2 + 1] = p1;
                psum += p0 + p1;
            }
            lpart[s] = lpart[s] * corr + psum;
            #pragma unroll
            for (int ntd = 0; ntd < 4; ntd++) {
                out[mt][ntd][hf * 2]     *= corr;
                out[mt][ntd][hf * 2 + 1] *= corr;
            }
        }

        // ---- PV: out += P @ V   (P in sc, V^T in smem)
        #pragma unroll
        for (int ktpv = 0; ktpv < 2; ktpv++) {
            uint32_t pah[2][4], pal[2][4];
            #pragma unroll
            for (int mt = 0; mt < 2; mt++) {
                split2(sc[mt][2 * ktpv][0],     sc[mt][2 * ktpv][1],
                       pah[mt][0], pal[mt][0]);
                split2(sc[mt][2 * ktpv][2],     sc[mt][2 * ktpv][3],
                       pah[mt][1], pal[mt][1]);
                split2(sc[mt][2 * ktpv + 1][0], sc[mt][2 * ktpv + 1][1],
                       pah[mt][2], pal[mt][2]);
                split2(sc[mt][2 * ktpv + 1][2], sc[mt][2 * ktpv + 1][3],
                       pah[mt][3], pal[mt][3]);
            }
            uint32_t vh[4][2], vl[4][2];
            #pragma unroll
            for (int ntd = 0; ntd < 4; ntd++) {
                int off = (b_row + ntd * 8) * 40 + b_col + ktpv * 16;
                ldmx2(vh[ntd], vh_base + off * 2);
                ldmx2(vl[ntd], vl_base + off * 2);
            }
            #pragma unroll
            for (int mt = 0; mt < 2; mt++)
                #pragma unroll
                for (int ntd = 0; ntd < 4; ntd++) {
                    mma16816(out[mt][ntd], pah[mt], vh[ntd]);
                    mma16816(out[mt][ntd], pah[mt], vl[ntd]);
                    mma16816(out[mt][ntd], pal[mt], vh[ntd]);
                }
        }
    }

    // ---- finalize: 1/lsum, write split-format A
    float inv[4];
    #pragma unroll
    for (int s = 0; s < 4; s++) {
        float ls = lpart[s];
        ls += __shfl_xor_sync(0xffffffffu, ls, 1);
        ls += __shfl_xor_sync(0xffffffffu, ls, 2);
        inv[s] = 1.f / ls;
    }
    #pragma unroll
    for (int mt = 0; mt < 2; mt++)
        #pragma unroll
        for (int ntd = 0; ntd < 4; ntd++) {
            int r0 = qbase + mt * 16 + (lane >> 2);
            int c  = h * 32 + ntd * 8 + (lane & 3) * 2;
            size_t base = (size_t)n * LSEQ * 256;
            float v00 = out[mt][ntd][0] * inv[mt * 2];
            float v01 = out[mt][ntd][1] * inv[mt * 2];
            float v10 = out[mt][ntd][2] * inv[mt * 2 + 1];
            float v11 = out[mt][ntd][3] * inv[mt * 2 + 1];
            *reinterpret_cast<uint2*>(&Aout[base + (size_t)r0 * 256 + c]) =
                make_uint2(splitpack(v00), splitpack(v01));
            *reinterpret_cast<uint2*>(&Aout[base + (size_t)(r0 + 8) * 256 + c]) =
                make_uint2(splitpack(v10), splitpack(v11));
        }
}

// ---------------------------------------------------------------------------
// Softmax pooling over L per (n, d):  out[n,d] = sum_l O[n,l,d]*softmax_l(O)
// ---------------------------------------------------------------------------
__global__ __launch_bounds__(256) void pool_kernel(
    const float* __restrict__ O, float* __restrict__ out)
{
    const int n  = blockIdx.y;
    const int d0 = blockIdx.x * 32;
    const int dc = threadIdx.x & 31;
    const int g  = threadIdx.x >> 5;
    const int d  = d0 + dc;

    float m = -INFINITY, se = 0.f, sex = 0.f;
    for (int l = g; l < LSEQ; l += 8) {
        float x = O[((size_t)n * LSEQ + l) * DDIM + d];
        if (x > m) {
            float c = __expf(m - x);
            se *= c; sex *= c; m = x;
        }
        float p = __expf(x - m);
        se += p; sex += p * x;
    }

    __shared__ float sm[8][32], sse[8][32], ssex[8][32];
    sm[g][dc] = m; sse[g][dc] = se; ssex[g][dc] = sex;
    __syncthreads();

    if (g == 0) {
        #pragma unroll
        for (int o = 1; o < 8; o++) {
            float m2 = sm[o][dc], se2 = sse[o][dc], sex2 = ssex[o][dc];
            if (m2 > m) {
                float c = __expf(m - m2);
                se *= c; sex *= c; m = m2;
            }
            float c2 = __expf(m2 - m);
            se += se2 * c2; sex += sex2 * c2;
        }
        out[(size_t)n * DDIM + d] = sex / se;
    }
}

// ---------------------------------------------------------------------------
// Launch
// ---------------------------------------------------------------------------
extern "C" void kernel_launch(void* const* d_in, const int* in_sizes, int n_in,
                              void* d_out, int out_size)
{
    const float* x  = (const float*)d_in[0];
    const float* Wq = (const float*)d_in[1];
    const float* bq = (const float*)d_in[2];
    const float* Wk = (const float*)d_in[3];
    const float* bk = (const float*)d_in[4];
    const float* Wv = (const float*)d_in[5];
    const float* bv = (const float*)d_in[6];
    const float* Wo = (const float*)d_in[7];
    const float* bo = (const float*)d_in[8];
    float* out = (float*)d_out;

    uint32_t *X2, *Q2, *K2, *V2, *A2, *Wq2, *Wk2, *Wv2, *Wo2;
    float* O;
    cudaGetSymbolAddress((void**)&X2, g_X2);
    cudaGetSymbolAddress((void**)&Q2, g_Q2);
    cudaGetSymbolAddress((void**)&K2, g_K2);
    cudaGetSymbolAddress((void**)&V2, g_V2);
    cudaGetSymbolAddress((void**)&A2, g_A2);
    cudaGetSymbolAddress((void**)&Wq2, g_Wq2);
    cudaGetSymbolAddress((void**)&Wk2, g_Wk2);
    cudaGetSymbolAddress((void**)&Wv2, g_Wv2);
    cudaGetSymbolAddress((void**)&Wo2, g_Wo2);
    cudaGetSymbolAddress((void**)&O, g_O);

    const float qscale = 0.17677669529663687f;   // 1/sqrt(32)

    split_kernel<<<MROWS * DDIM / 256, 256>>>(x, X2, MROWS * DDIM);
    split_kernel<<<DDIM * DDIM / 256, 256>>>(Wq, Wq2, DDIM * DDIM);
    split_kernel<<<DDIM * DDIM / 256, 256>>>(Wk, Wk2, DDIM * DDIM);
    split_kernel<<<DDIM * DDIM / 256, 256>>>(Wv, Wv2, DDIM * DDIM);
    split_kernel<<<DDIM * DDIM / 256, 256>>>(Wo, Wo2, DDIM * DDIM);

    dim3 gGrid(2, MROWS / 128);     // (n-blocks, m-blocks)
    gemm_mma<<<gGrid, 256>>>(X2, Wq2, bq, Q2, qscale, 1);
    gemm_mma<<<gGrid, 256>>>(X2, Wk2, bk, K2, 1.f, 1);
    gemm_mma<<<gGrid, 256>>>(X2, Wv2, bv, V2, 1.f, 1);

    dim3 aGrid(LSEQ / 128, NHEAD, NSEQ);   // (8, 8, 16)
    attn_mma<<<aGrid, 128>>>(Q2, K2, V2, A2);

    gemm_mma<<<gGrid, 256>>>(A2, Wo2, bo, O, 1.f, 0);

    dim3 pGrid(DDIM / 32, NSEQ);
    pool_kernel<<<pGrid, 256>>>(O, out);
}